// round 2
// baseline (speedup 1.0000x reference)
#include <cuda_runtime.h>

// Problem constants
#define HW    115200      // 240*480
#define HW4   28800       // HW/4
#define C_    128
#define L_    4
#define R_    8
#define KK    36
#define CH    64
#define WF    (C_*R_ + R_*KK)   // 1312

// Scratch (allocation-free: __device__ globals)
__device__ float g_ctx[L_*C_];
__device__ float g_W1[L_*C_*R_];
__device__ float g_W2[L_*R_*KK];

// -------------------------------------------------------------------------
// K1: ctx[l,c] = mean over HW of x[l,c,:,:].  512 blocks, one per (l,c).
// -------------------------------------------------------------------------
__global__ void mean_kernel(const float* __restrict__ x) {
    const int lc = blockIdx.x;
    const float4* xp = reinterpret_cast<const float4*>(x + (size_t)lc * HW);
    float s = 0.f;
    for (int i = threadIdx.x; i < HW4; i += blockDim.x) {
        float4 v = xp[i];
        s += (v.x + v.y) + (v.z + v.w);
    }
    __shared__ float red[8];
    #pragma unroll
    for (int o = 16; o; o >>= 1) s += __shfl_down_sync(0xffffffffu, s, o);
    if ((threadIdx.x & 31) == 0) red[threadIdx.x >> 5] = s;
    __syncthreads();
    if (threadIdx.x < 8) {
        s = red[threadIdx.x];
        #pragma unroll
        for (int o = 4; o; o >>= 1) s += __shfl_down_sync(0xffu, s, o);
        if (threadIdx.x == 0) g_ctx[lc] = s * (1.0f / (float)HW);
    }
}

// -------------------------------------------------------------------------
// K2: hypernet. One block, 256 threads.
//   h  = silu(ctx @ Wa + ba)           (4,64)
//   wf = h @ Wb + bb                   (4,1312)
//   W1 = wf[:, :1024].reshape(4,128,8), W2 = wf[:, 1024:].reshape(4,8,36)
// -------------------------------------------------------------------------
__global__ void hyper_kernel(const float* __restrict__ Wa,
                             const float* __restrict__ ba,
                             const float* __restrict__ Wb,
                             const float* __restrict__ bb) {
    __shared__ float ctx_s[L_*C_];
    __shared__ float h_s[L_*CH];
    const int tid = threadIdx.x;

    for (int i = tid; i < L_*C_; i += 256) ctx_s[i] = g_ctx[i];
    __syncthreads();

    // 256 threads == 4*64 outputs of h
    {
        const int l = tid / CH, j = tid % CH;
        float acc = ba[j];
        #pragma unroll 8
        for (int c = 0; c < C_; c++) acc += ctx_s[l*C_ + c] * Wa[c*CH + j];
        float sg = 1.f / (1.f + expf(-acc));
        h_s[l*CH + j] = acc * sg;
    }
    __syncthreads();

    for (int idx = tid; idx < L_*WF; idx += 256) {
        const int l = idx / WF, o = idx % WF;
        float acc = bb[o];
        #pragma unroll 8
        for (int j = 0; j < CH; j++) acc += h_s[l*CH + j] * Wb[j*WF + o];
        if (o < C_*R_) g_W1[l*C_*R_ + o] = acc;
        else           g_W2[l*R_*KK + (o - C_*R_)] = acc;
    }
}

// -------------------------------------------------------------------------
// K3: out = x + gain[c] * (W1 @ (W2 @ Y)).
// Per thread: one float4 of pixels; z[r] = sum_k W2[l,r,k]*Y[k,p] kept in
// registers, amortized over the 128-channel loop (8 FMA/element).
// grid = (ceil(HW4/256), L_), 256 threads.
// -------------------------------------------------------------------------
__global__ void __launch_bounds__(256)
apply_kernel(const float* __restrict__ x,
             const float* __restrict__ Y,
             const float* __restrict__ gain,
             float* __restrict__ out) {
    const int l = blockIdx.y;

    __shared__ float w1s[C_*R_];
    __shared__ float w2s[R_*KK];
    __shared__ float gs[C_];
    for (int i = threadIdx.x; i < C_*R_; i += 256) w1s[i] = g_W1[l*C_*R_ + i];
    for (int i = threadIdx.x; i < R_*KK; i += 256) w2s[i] = g_W2[l*R_*KK + i];
    if (threadIdx.x < C_) gs[threadIdx.x] = gain[threadIdx.x];
    __syncthreads();

    const int p4 = blockIdx.x * 256 + threadIdx.x;
    if (p4 >= HW4) return;

    const float4* Y4 = reinterpret_cast<const float4*>(Y);

    float4 z[R_];
    #pragma unroll
    for (int r = 0; r < R_; r++) z[r] = make_float4(0.f, 0.f, 0.f, 0.f);

    #pragma unroll
    for (int k = 0; k < KK; k++) {
        float4 y = Y4[(size_t)k * HW4 + p4];
        #pragma unroll
        for (int r = 0; r < R_; r++) {
            float w = w2s[r*KK + k];
            z[r].x = fmaf(w, y.x, z[r].x);
            z[r].y = fmaf(w, y.y, z[r].y);
            z[r].z = fmaf(w, y.z, z[r].z);
            z[r].w = fmaf(w, y.w, z[r].w);
        }
    }

    const float4* x4 = reinterpret_cast<const float4*>(x);
    float4*       o4 = reinterpret_cast<float4*>(out);
    const size_t base = (size_t)l * C_ * HW4 + p4;

    #pragma unroll 4
    for (int c = 0; c < C_; c++) {
        float4 xv = x4[base + (size_t)c * HW4];
        float4 acc = make_float4(0.f, 0.f, 0.f, 0.f);
        #pragma unroll
        for (int r = 0; r < R_; r++) {
            float w = w1s[c*R_ + r];
            acc.x = fmaf(w, z[r].x, acc.x);
            acc.y = fmaf(w, z[r].y, acc.y);
            acc.z = fmaf(w, z[r].z, acc.z);
            acc.w = fmaf(w, z[r].w, acc.w);
        }
        const float g = gs[c];
        xv.x = fmaf(g, acc.x, xv.x);
        xv.y = fmaf(g, acc.y, xv.y);
        xv.z = fmaf(g, acc.z, xv.z);
        xv.w = fmaf(g, acc.w, xv.w);
        o4[base + (size_t)c * HW4] = xv;
    }
}

// -------------------------------------------------------------------------
// launch
// Inputs (metadata order): x, Wa, ba, Wb, bb, gain, Y  (all float32)
// -------------------------------------------------------------------------
extern "C" void kernel_launch(void* const* d_in, const int* in_sizes, int n_in,
                              void* d_out, int out_size) {
    const float* x    = (const float*)d_in[0];
    const float* Wa   = (const float*)d_in[1];
    const float* ba   = (const float*)d_in[2];
    const float* Wb   = (const float*)d_in[3];
    const float* bb   = (const float*)d_in[4];
    const float* gain = (const float*)d_in[5];
    const float* Y    = (const float*)d_in[6];
    float* out = (float*)d_out;

    mean_kernel<<<L_*C_, 256>>>(x);
    hyper_kernel<<<1, 256>>>(Wa, ba, Wb, bb);
    dim3 grid((HW4 + 255) / 256, L_);
    apply_kernel<<<grid, 256>>>(x, Y, gain, out);
}

// round 3
// speedup vs baseline: 1.0633x; 1.0633x over previous
#include <cuda_runtime.h>

// Problem constants
#define HW    115200      // 240*480
#define HW4   28800       // HW/4
#define C_    128
#define L_    4
#define R_    8
#define KK    36
#define CH    64
#define WF    (C_*R_ + R_*KK)   // 1312

// Scratch (allocation-free: __device__ globals)
__device__ float g_ctx[L_*C_];
__device__ float g_W1[L_*C_*R_];          // pre-scaled by gain[c]
__device__ float g_W2[L_*R_*KK];
__device__ float g_Z[L_*R_*HW];           // Z[l,r,p] = sum_k W2[l,r,k]*Y[k,p]  (14.7 MB)

// -------------------------------------------------------------------------
// K1: ctx[l,c] = mean over HW of x[l,c,:,:].  512 blocks x 512 threads.
// -------------------------------------------------------------------------
__global__ void __launch_bounds__(512)
mean_kernel(const float* __restrict__ x) {
    const int lc = blockIdx.x;
    const float4* xp = reinterpret_cast<const float4*>(x + (size_t)lc * HW);
    float s = 0.f;
    #pragma unroll 4
    for (int i = threadIdx.x; i < HW4; i += 512) {
        float4 v = xp[i];
        s += (v.x + v.y) + (v.z + v.w);
    }
    __shared__ float red[16];
    #pragma unroll
    for (int o = 16; o; o >>= 1) s += __shfl_down_sync(0xffffffffu, s, o);
    if ((threadIdx.x & 31) == 0) red[threadIdx.x >> 5] = s;
    __syncthreads();
    if (threadIdx.x < 16) {
        s = red[threadIdx.x];
        #pragma unroll
        for (int o = 8; o; o >>= 1) s += __shfl_down_sync(0xffffu, s, o);
        if (threadIdx.x == 0) g_ctx[lc] = s * (1.0f / (float)HW);
    }
}

// -------------------------------------------------------------------------
// K2: hypernet. One block, 256 threads.
//   h  = silu(ctx @ Wa + ba); wf = h @ Wb + bb
//   g_W1[l,c,r] = gain[c] * wf[:1024];  g_W2 = wf[1024:]
// -------------------------------------------------------------------------
__global__ void hyper_kernel(const float* __restrict__ Wa,
                             const float* __restrict__ ba,
                             const float* __restrict__ Wb,
                             const float* __restrict__ bb,
                             const float* __restrict__ gain) {
    __shared__ float ctx_s[L_*C_];
    __shared__ float h_s[L_*CH];
    const int tid = threadIdx.x;

    for (int i = tid; i < L_*C_; i += 256) ctx_s[i] = g_ctx[i];
    __syncthreads();

    {
        const int l = tid / CH, j = tid % CH;
        float acc = ba[j];
        #pragma unroll 8
        for (int c = 0; c < C_; c++) acc += ctx_s[l*C_ + c] * Wa[c*CH + j];
        float sg = 1.f / (1.f + expf(-acc));
        h_s[l*CH + j] = acc * sg;
    }
    __syncthreads();

    for (int idx = tid; idx < L_*WF; idx += 256) {
        const int l = idx / WF, o = idx % WF;
        float acc = bb[o];
        #pragma unroll 8
        for (int j = 0; j < CH; j++) acc += h_s[l*CH + j] * Wb[j*WF + o];
        if (o < C_*R_) g_W1[l*C_*R_ + o] = acc * gain[o / R_];
        else           g_W2[l*R_*KK + (o - C_*R_)] = acc;
    }
}

// -------------------------------------------------------------------------
// K2b: Z[l,r,p] = sum_k W2[l,r,k] * Y[k,p].  grid (HW4/128, L_), 128 thr.
// Traffic: Y 16.6MB (DRAM once, then L2) + Z 14.7MB write.
// -------------------------------------------------------------------------
__global__ void __launch_bounds__(128)
zcomp_kernel(const float* __restrict__ Y) {
    const int l  = blockIdx.y;
    const int p4 = blockIdx.x * 128 + threadIdx.x;

    __shared__ float w2s[R_*KK];
    for (int i = threadIdx.x; i < R_*KK; i += 128) w2s[i] = g_W2[l*R_*KK + i];
    __syncthreads();

    const float4* Y4 = reinterpret_cast<const float4*>(Y);
    float4 z[R_];
    #pragma unroll
    for (int r = 0; r < R_; r++) z[r] = make_float4(0.f, 0.f, 0.f, 0.f);

    #pragma unroll
    for (int k = 0; k < KK; k++) {
        float4 y = Y4[(size_t)k * HW4 + p4];
        #pragma unroll
        for (int r = 0; r < R_; r++) {
            float w = w2s[r*KK + k];
            z[r].x = fmaf(w, y.x, z[r].x);
            z[r].y = fmaf(w, y.y, z[r].y);
            z[r].z = fmaf(w, y.z, z[r].z);
            z[r].w = fmaf(w, y.w, z[r].w);
        }
    }

    float4* Z4 = reinterpret_cast<float4*>(g_Z);
    #pragma unroll
    for (int r = 0; r < R_; r++)
        Z4[(size_t)(l*R_ + r) * HW4 + p4] = z[r];
}

// -------------------------------------------------------------------------
// K3: out = x + (gain*W1) @ Z.  grid (ceil(HW4/256), L_, 2), 256 thr.
// Each block: 64 channels. c-loop batched x8: 8 front-batched loads (MLP=8),
// then compute+store. z[8] float4 read once from L2.
// -------------------------------------------------------------------------
__global__ void __launch_bounds__(256)
apply_kernel(const float* __restrict__ x,
             float* __restrict__ out) {
    const int l  = blockIdx.y;
    const int c0 = blockIdx.z * (C_/2);   // 0 or 64

    __shared__ float w1s[(C_/2)*R_];
    for (int i = threadIdx.x; i < (C_/2)*R_; i += 256)
        w1s[i] = g_W1[l*C_*R_ + c0*R_ + i];
    __syncthreads();

    const int p4 = blockIdx.x * 256 + threadIdx.x;
    if (p4 >= HW4) return;

    const float4* Z4 = reinterpret_cast<const float4*>(g_Z);
    float4 z[R_];
    #pragma unroll
    for (int r = 0; r < R_; r++)
        z[r] = Z4[(size_t)(l*R_ + r) * HW4 + p4];

    const float4* x4 = reinterpret_cast<const float4*>(x);
    float4*       o4 = reinterpret_cast<float4*>(out);
    const size_t base = ((size_t)l * C_ + c0) * HW4 + p4;

    for (int cc = 0; cc < C_/2; cc += 8) {
        float4 xv[8];
        #pragma unroll
        for (int j = 0; j < 8; j++)
            xv[j] = x4[base + (size_t)(cc + j) * HW4];
        #pragma unroll
        for (int j = 0; j < 8; j++) {
            float4 acc = make_float4(0.f, 0.f, 0.f, 0.f);
            const int c = cc + j;
            #pragma unroll
            for (int r = 0; r < R_; r++) {
                float w = w1s[c*R_ + r];
                acc.x = fmaf(w, z[r].x, acc.x);
                acc.y = fmaf(w, z[r].y, acc.y);
                acc.z = fmaf(w, z[r].z, acc.z);
                acc.w = fmaf(w, z[r].w, acc.w);
            }
            xv[j].x += acc.x;
            xv[j].y += acc.y;
            xv[j].z += acc.z;
            xv[j].w += acc.w;
            o4[base + (size_t)c * HW4] = xv[j];
        }
    }
}

// -------------------------------------------------------------------------
// launch.  Inputs (metadata order): x, Wa, ba, Wb, bb, gain, Y  (all f32)
// -------------------------------------------------------------------------
extern "C" void kernel_launch(void* const* d_in, const int* in_sizes, int n_in,
                              void* d_out, int out_size) {
    const float* x    = (const float*)d_in[0];
    const float* Wa   = (const float*)d_in[1];
    const float* ba   = (const float*)d_in[2];
    const float* Wb   = (const float*)d_in[3];
    const float* bb   = (const float*)d_in[4];
    const float* gain = (const float*)d_in[5];
    const float* Y    = (const float*)d_in[6];
    float* out = (float*)d_out;

    mean_kernel<<<L_*C_, 512>>>(x);
    hyper_kernel<<<1, 256>>>(Wa, ba, Wb, bb, gain);
    zcomp_kernel<<<dim3(HW4/128, L_), 128>>>(Y);
    apply_kernel<<<dim3((HW4 + 255)/256, L_, 2), 256>>>(x, out);
}

// round 4
// speedup vs baseline: 1.3128x; 1.2347x over previous
#include <cuda_runtime.h>

// Problem constants
#define HW    115200      // 240*480
#define HW4   28800       // HW/4
#define C_    128
#define L_    4
#define R_    8
#define KK    36
#define CH    64
#define WF    (C_*R_ + R_*KK)   // 1312

// Scratch (allocation-free: __device__ globals)
__device__ float g_ctx[L_*C_];
__device__ float g_h[L_*CH];
__device__ float g_W1[L_*C_*R_];          // pre-scaled by gain[c]
__device__ float g_W2[L_*R_*KK];
__device__ float g_Z[L_*R_*HW];           // Z[l,r,p] = sum_k W2[l,r,k]*Y[k,p]

// -------------------------------------------------------------------------
// K1: ctx[l,c] = mean over HW of x[l,c,:,:].  512 blocks x 256 threads.
// (Proven 39.4us @ 76.9% DRAM in R1.)
// -------------------------------------------------------------------------
__global__ void __launch_bounds__(256)
mean_kernel(const float* __restrict__ x) {
    const int lc = blockIdx.x;
    const float4* xp = reinterpret_cast<const float4*>(x + (size_t)lc * HW);
    float s = 0.f;
    for (int i = threadIdx.x; i < HW4; i += 256) {
        float4 v = xp[i];
        s += (v.x + v.y) + (v.z + v.w);
    }
    __shared__ float red[8];
    #pragma unroll
    for (int o = 16; o; o >>= 1) s += __shfl_down_sync(0xffffffffu, s, o);
    if ((threadIdx.x & 31) == 0) red[threadIdx.x >> 5] = s;
    __syncthreads();
    if (threadIdx.x < 8) {
        s = red[threadIdx.x];
        #pragma unroll
        for (int o = 4; o; o >>= 1) s += __shfl_down_sync(0xffu, s, o);
        if (threadIdx.x == 0) g_ctx[lc] = s * (1.0f / (float)HW);
    }
}

// -------------------------------------------------------------------------
// K2a: h = silu(ctx @ Wa + ba).  1 block, 256 threads (one per (l,j)).
// -------------------------------------------------------------------------
__global__ void __launch_bounds__(256)
h_kernel(const float* __restrict__ Wa, const float* __restrict__ ba) {
    __shared__ float ctx_s[L_*C_];
    const int tid = threadIdx.x;
    for (int i = tid; i < L_*C_; i += 256) ctx_s[i] = g_ctx[i];
    __syncthreads();
    const int l = tid / CH, j = tid % CH;
    float acc = ba[j];
    #pragma unroll 8
    for (int c = 0; c < C_; c++) acc += ctx_s[l*C_ + c] * Wa[c*CH + j];
    float sg = 1.f / (1.f + expf(-acc));
    g_h[l*CH + j] = acc * sg;
}

// -------------------------------------------------------------------------
// K2b: wf = h @ Wb + bb -> W1 (gain-folded), W2.
// 21 blocks x 256 threads: one output each (5248 outputs).
// -------------------------------------------------------------------------
__global__ void __launch_bounds__(256)
wf_kernel(const float* __restrict__ Wb, const float* __restrict__ bb,
          const float* __restrict__ gain) {
    const int idx = blockIdx.x * 256 + threadIdx.x;
    if (idx >= L_*WF) return;
    const int l = idx / WF, o = idx % WF;

    __shared__ float h_s[L_*CH];
    for (int i = threadIdx.x; i < L_*CH; i += 256) h_s[i] = g_h[i];
    __syncthreads();

    float acc = bb[o];
    #pragma unroll 8
    for (int j = 0; j < CH; j++) acc += h_s[l*CH + j] * Wb[j*WF + o];
    if (o < C_*R_) g_W1[l*C_*R_ + o] = acc * gain[o / R_];
    else           g_W2[l*R_*KK + (o - C_*R_)] = acc;
}

// -------------------------------------------------------------------------
// K2c: Z[l,r,p] = sum_k W2[l,r,k] * Y[k,p].  grid (225, 4), 128 threads.
// Explicit k-chunking (9 x 4 loads) keeps live regs ~55 -> no spills.
// -------------------------------------------------------------------------
__global__ void __launch_bounds__(128)
zcomp_kernel(const float* __restrict__ Y) {
    const int l  = blockIdx.y;
    const int p4 = blockIdx.x * 128 + threadIdx.x;

    __shared__ float w2s[R_*KK];
    for (int i = threadIdx.x; i < R_*KK; i += 128) w2s[i] = g_W2[l*R_*KK + i];
    __syncthreads();

    const float4* Y4 = reinterpret_cast<const float4*>(Y);
    float4 z[R_];
    #pragma unroll
    for (int r = 0; r < R_; r++) z[r] = make_float4(0.f, 0.f, 0.f, 0.f);

    for (int kc = 0; kc < KK; kc += 4) {          // 9 chunks, not unrolled
        float4 y[4];
        #pragma unroll
        for (int j = 0; j < 4; j++)
            y[j] = Y4[(size_t)(kc + j) * HW4 + p4];
        #pragma unroll
        for (int j = 0; j < 4; j++) {
            #pragma unroll
            for (int r = 0; r < R_; r++) {
                float w = w2s[r*KK + kc + j];
                z[r].x = fmaf(w, y[j].x, z[r].x);
                z[r].y = fmaf(w, y[j].y, z[r].y);
                z[r].z = fmaf(w, y[j].z, z[r].z);
                z[r].w = fmaf(w, y[j].w, z[r].w);
            }
        }
    }

    float4* Z4 = reinterpret_cast<float4*>(g_Z);
    #pragma unroll
    for (int r = 0; r < R_; r++)
        Z4[(size_t)(l*R_ + r) * HW4 + p4] = z[r];
}

// -------------------------------------------------------------------------
// K3: out = x + (gain*W1) @ Z.  UNCHANGED from R2 (measured 75.5us,
// 5965 GB/s = 98% of achieved-DRAM ceiling).
// -------------------------------------------------------------------------
__global__ void __launch_bounds__(256)
apply_kernel(const float* __restrict__ x,
             float* __restrict__ out) {
    const int l  = blockIdx.y;
    const int c0 = blockIdx.z * (C_/2);   // 0 or 64

    __shared__ float w1s[(C_/2)*R_];
    for (int i = threadIdx.x; i < (C_/2)*R_; i += 256)
        w1s[i] = g_W1[l*C_*R_ + c0*R_ + i];
    __syncthreads();

    const int p4 = blockIdx.x * 256 + threadIdx.x;
    if (p4 >= HW4) return;

    const float4* Z4 = reinterpret_cast<const float4*>(g_Z);
    float4 z[R_];
    #pragma unroll
    for (int r = 0; r < R_; r++)
        z[r] = Z4[(size_t)(l*R_ + r) * HW4 + p4];

    const float4* x4 = reinterpret_cast<const float4*>(x);
    float4*       o4 = reinterpret_cast<float4*>(out);
    const size_t base = ((size_t)l * C_ + c0) * HW4 + p4;

    for (int cc = 0; cc < C_/2; cc += 8) {
        float4 xv[8];
        #pragma unroll
        for (int j = 0; j < 8; j++)
            xv[j] = x4[base + (size_t)(cc + j) * HW4];
        #pragma unroll
        for (int j = 0; j < 8; j++) {
            float4 acc = make_float4(0.f, 0.f, 0.f, 0.f);
            const int c = cc + j;
            #pragma unroll
            for (int r = 0; r < R_; r++) {
                float w = w1s[c*R_ + r];
                acc.x = fmaf(w, z[r].x, acc.x);
                acc.y = fmaf(w, z[r].y, acc.y);
                acc.z = fmaf(w, z[r].z, acc.z);
                acc.w = fmaf(w, z[r].w, acc.w);
            }
            xv[j].x += acc.x;
            xv[j].y += acc.y;
            xv[j].z += acc.z;
            xv[j].w += acc.w;
            o4[base + (size_t)c * HW4] = xv[j];
        }
    }
}

// -------------------------------------------------------------------------
// launch.  Inputs (metadata order): x, Wa, ba, Wb, bb, gain, Y  (all f32)
// -------------------------------------------------------------------------
extern "C" void kernel_launch(void* const* d_in, const int* in_sizes, int n_in,
                              void* d_out, int out_size) {
    const float* x    = (const float*)d_in[0];
    const float* Wa   = (const float*)d_in[1];
    const float* ba   = (const float*)d_in[2];
    const float* Wb   = (const float*)d_in[3];
    const float* bb   = (const float*)d_in[4];
    const float* gain = (const float*)d_in[5];
    const float* Y    = (const float*)d_in[6];
    float* out = (float*)d_out;

    mean_kernel<<<L_*C_, 256>>>(x);
    h_kernel<<<1, 256>>>(Wa, ba);
    wf_kernel<<<(L_*WF + 255)/256, 256>>>(Wb, bb, gain);
    zcomp_kernel<<<dim3(HW4/128, L_), 128>>>(Y);
    apply_kernel<<<dim3((HW4 + 255)/256, L_, 2), 256>>>(x, out);
}

// round 5
// speedup vs baseline: 1.3712x; 1.0445x over previous
#include <cuda_runtime.h>

// Problem constants
#define HW    115200      // 240*480
#define HW4   28800       // HW/4
#define C_    128
#define L_    4
#define R_    8
#define KK    36
#define CH    64
#define WF    (C_*R_ + R_*KK)   // 1312

// Scratch (allocation-free: __device__ globals)
__device__ float g_ctx[L_*C_];
__device__ float g_W1[L_*C_*R_];          // pre-scaled by gain[c]
__device__ float g_W2[L_*R_*KK];

// -------------------------------------------------------------------------
// K1: ctx[l,c] = mean over HW of x[l,c,:,:].  512 blocks x 256 threads.
// (Proven 39.4us @ 76.9% DRAM.)
// -------------------------------------------------------------------------
__global__ void __launch_bounds__(256)
mean_kernel(const float* __restrict__ x) {
    const int lc = blockIdx.x;
    const float4* xp = reinterpret_cast<const float4*>(x + (size_t)lc * HW);
    float s = 0.f;
    for (int i = threadIdx.x; i < HW4; i += 256) {
        float4 v = xp[i];
        s += (v.x + v.y) + (v.z + v.w);
    }
    __shared__ float red[8];
    #pragma unroll
    for (int o = 16; o; o >>= 1) s += __shfl_down_sync(0xffffffffu, s, o);
    if ((threadIdx.x & 31) == 0) red[threadIdx.x >> 5] = s;
    __syncthreads();
    if (threadIdx.x < 8) {
        s = red[threadIdx.x];
        #pragma unroll
        for (int o = 4; o; o >>= 1) s += __shfl_down_sync(0xffu, s, o);
        if (threadIdx.x == 0) g_ctx[lc] = s * (1.0f / (float)HW);
    }
}

// -------------------------------------------------------------------------
// K2: full hypernet in ONE kernel. 21 blocks x 256 threads.
// Every block redundantly computes h = silu(ctx@Wa+ba) into smem (cheap:
// 128 MACs/thread), then computes its own 256 outputs of wf = h@Wb+bb.
// -------------------------------------------------------------------------
__global__ void __launch_bounds__(256)
hyper_kernel(const float* __restrict__ Wa, const float* __restrict__ ba,
             const float* __restrict__ Wb, const float* __restrict__ bb,
             const float* __restrict__ gain) {
    __shared__ float ctx_s[L_*C_];
    __shared__ float h_s[L_*CH];
    const int tid = threadIdx.x;

    for (int i = tid; i < L_*C_; i += 256) ctx_s[i] = g_ctx[i];
    __syncthreads();

    {   // h: 256 threads == 4*64 outputs
        const int l = tid / CH, j = tid % CH;
        float acc = ba[j];
        #pragma unroll 8
        for (int c = 0; c < C_; c++) acc += ctx_s[l*C_ + c] * Wa[c*CH + j];
        float sg = 1.f / (1.f + expf(-acc));
        h_s[l*CH + j] = acc * sg;
    }
    __syncthreads();

    const int idx = blockIdx.x * 256 + tid;
    if (idx >= L_*WF) return;
    const int l = idx / WF, o = idx % WF;
    float acc = bb[o];
    #pragma unroll 8
    for (int j = 0; j < CH; j++) acc += h_s[l*CH + j] * Wb[j*WF + o];
    if (o < C_*R_) g_W1[l*C_*R_ + o] = acc * gain[o / R_];
    else           g_W2[l*R_*KK + (o - C_*R_)] = acc;
}

// -------------------------------------------------------------------------
// K3: out = x + (gain*W1) @ (W2 @ Y), fused.
// grid (ceil(HW4/256), L_, 2), 256 threads. Each block: 64 channels.
// Prologue: z[r] = sum_k w2s[r,k]*Y[k,p] in registers (9 chunks x 4 loads,
// Y is L2-resident after the first wave). Then the proven R2 c-loop
// (8 front-batched x loads -> MLP=8).
// -------------------------------------------------------------------------
__global__ void __launch_bounds__(256)
apply_kernel(const float* __restrict__ x,
             const float* __restrict__ Y,
             float* __restrict__ out) {
    const int l  = blockIdx.y;
    const int c0 = blockIdx.z * (C_/2);   // 0 or 64

    __shared__ float w1s[(C_/2)*R_];
    __shared__ float w2s[R_*KK];
    for (int i = threadIdx.x; i < (C_/2)*R_; i += 256)
        w1s[i] = g_W1[l*C_*R_ + c0*R_ + i];
    for (int i = threadIdx.x; i < R_*KK; i += 256)
        w2s[i] = g_W2[l*R_*KK + i];
    __syncthreads();

    const int p4 = blockIdx.x * 256 + threadIdx.x;
    if (p4 >= HW4) return;

    const float4* Y4 = reinterpret_cast<const float4*>(Y);
    float4 z[R_];
    #pragma unroll
    for (int r = 0; r < R_; r++) z[r] = make_float4(0.f, 0.f, 0.f, 0.f);

    for (int kc = 0; kc < KK; kc += 4) {          // 9 chunks, not unrolled
        float4 y[4];
        #pragma unroll
        for (int j = 0; j < 4; j++)
            y[j] = Y4[(size_t)(kc + j) * HW4 + p4];
        #pragma unroll
        for (int j = 0; j < 4; j++) {
            #pragma unroll
            for (int r = 0; r < R_; r++) {
                float w = w2s[r*KK + kc + j];
                z[r].x = fmaf(w, y[j].x, z[r].x);
                z[r].y = fmaf(w, y[j].y, z[r].y);
                z[r].z = fmaf(w, y[j].z, z[r].z);
                z[r].w = fmaf(w, y[j].w, z[r].w);
            }
        }
    }

    const float4* x4 = reinterpret_cast<const float4*>(x);
    float4*       o4 = reinterpret_cast<float4*>(out);
    const size_t base = ((size_t)l * C_ + c0) * HW4 + p4;

    for (int cc = 0; cc < C_/2; cc += 8) {
        float4 xv[8];
        #pragma unroll
        for (int j = 0; j < 8; j++)
            xv[j] = x4[base + (size_t)(cc + j) * HW4];
        #pragma unroll
        for (int j = 0; j < 8; j++) {
            float4 acc = make_float4(0.f, 0.f, 0.f, 0.f);
            const int c = cc + j;
            #pragma unroll
            for (int r = 0; r < R_; r++) {
                float w = w1s[c*R_ + r];
                acc.x = fmaf(w, z[r].x, acc.x);
                acc.y = fmaf(w, z[r].y, acc.y);
                acc.z = fmaf(w, z[r].z, acc.z);
                acc.w = fmaf(w, z[r].w, acc.w);
            }
            xv[j].x += acc.x;
            xv[j].y += acc.y;
            xv[j].z += acc.z;
            xv[j].w += acc.w;
            o4[base + (size_t)c * HW4] = xv[j];
        }
    }
}

// -------------------------------------------------------------------------
// launch.  Inputs (metadata order): x, Wa, ba, Wb, bb, gain, Y  (all f32)
// -------------------------------------------------------------------------
extern "C" void kernel_launch(void* const* d_in, const int* in_sizes, int n_in,
                              void* d_out, int out_size) {
    const float* x    = (const float*)d_in[0];
    const float* Wa   = (const float*)d_in[1];
    const float* ba   = (const float*)d_in[2];
    const float* Wb   = (const float*)d_in[3];
    const float* bb   = (const float*)d_in[4];
    const float* gain = (const float*)d_in[5];
    const float* Y    = (const float*)d_in[6];
    float* out = (float*)d_out;

    mean_kernel<<<L_*C_, 256>>>(x);
    hyper_kernel<<<(L_*WF + 255)/256, 256>>>(Wa, ba, Wb, bb, gain);
    apply_kernel<<<dim3((HW4 + 255)/256, L_, 2), 256>>>(x, Y, out);
}

// round 8
// speedup vs baseline: 1.4752x; 1.0758x over previous
#include <cuda_runtime.h>

// Problem constants
#define HW    115200      // 240*480
#define HW4   28800       // HW/4
#define C_    128
#define L_    4
#define R_    8
#define KK    36
#define CH    64
#define WF    (C_*R_ + R_*KK)   // 1312

// Scratch (allocation-free: __device__ globals)
__device__ float g_ctx[L_*C_];
__device__ float g_W1[L_*C_*R_];          // pre-scaled by gain[c]
__device__ float g_W2[L_*R_*KK];

// -------------------------------------------------------------------------
// K1: ctx[l,c] = mean over HW of x[l,c,:,:].  512 blocks x 256 threads.
// (Proven ~40us @ ~76% DRAM — at achieved roofline.)
// -------------------------------------------------------------------------
__global__ void __launch_bounds__(256)
mean_kernel(const float* __restrict__ x) {
    const int lc = blockIdx.x;
    const float4* xp = reinterpret_cast<const float4*>(x + (size_t)lc * HW);
    float s = 0.f;
    for (int i = threadIdx.x; i < HW4; i += 256) {
        float4 v = xp[i];
        s += (v.x + v.y) + (v.z + v.w);
    }
    __shared__ float red[8];
    #pragma unroll
    for (int o = 16; o; o >>= 1) s += __shfl_down_sync(0xffffffffu, s, o);
    if ((threadIdx.x & 31) == 0) red[threadIdx.x >> 5] = s;
    __syncthreads();
    if (threadIdx.x < 8) {
        s = red[threadIdx.x];
        #pragma unroll
        for (int o = 4; o; o >>= 1) s += __shfl_down_sync(0xffu, s, o);
        if (threadIdx.x == 0) g_ctx[lc] = s * (1.0f / (float)HW);
    }
}

// -------------------------------------------------------------------------
// K2: full hypernet. 21 blocks x 256 threads; each block redundantly
// computes h in smem, then 256 wf outputs of its own.
// -------------------------------------------------------------------------
__global__ void __launch_bounds__(256)
hyper_kernel(const float* __restrict__ Wa, const float* __restrict__ ba,
             const float* __restrict__ Wb, const float* __restrict__ bb,
             const float* __restrict__ gain) {
    __shared__ float ctx_s[L_*C_];
    __shared__ float h_s[L_*CH];
    const int tid = threadIdx.x;

    for (int i = tid; i < L_*C_; i += 256) ctx_s[i] = g_ctx[i];
    __syncthreads();

    {   // h: 256 threads == 4*64 outputs
        const int l = tid / CH, j = tid % CH;
        float acc = ba[j];
        #pragma unroll 8
        for (int c = 0; c < C_; c++) acc += ctx_s[l*C_ + c] * Wa[c*CH + j];
        float sg = 1.f / (1.f + expf(-acc));
        h_s[l*CH + j] = acc * sg;
    }
    __syncthreads();

    const int idx = blockIdx.x * 256 + tid;
    if (idx >= L_*WF) return;
    const int l = idx / WF, o = idx % WF;
    float acc = bb[o];
    #pragma unroll 8
    for (int j = 0; j < CH; j++) acc += h_s[l*CH + j] * Wb[j*WF + o];
    if (o < C_*R_) g_W1[l*C_*R_ + o] = acc * gain[o / R_];
    else           g_W2[l*R_*KK + (o - C_*R_)] = acc;
}

// -------------------------------------------------------------------------
// K3: out = x + (gain*W1) @ (W2 @ Y), fused.
// grid (113, L_), 256 threads, occ-3 pinned. ONE block = ALL 128 channels:
// the z-prologue (36 Y loads, MLP=6 chunks) is paid once per (p-tile, l),
// then the proven 8-batched c-loop (MLP=8) runs 16 iterations.
// -------------------------------------------------------------------------
__global__ void __launch_bounds__(256, 3)
apply_kernel(const float* __restrict__ x,
             const float* __restrict__ Y,
             float* __restrict__ out) {
    const int l = blockIdx.y;

    __shared__ float w1s[C_*R_];
    __shared__ float w2s[R_*KK];
    for (int i = threadIdx.x; i < C_*R_; i += 256)
        w1s[i] = g_W1[l*C_*R_ + i];
    for (int i = threadIdx.x; i < R_*KK; i += 256)
        w2s[i] = g_W2[l*R_*KK + i];
    __syncthreads();

    const int p4 = blockIdx.x * 256 + threadIdx.x;
    if (p4 >= HW4) return;

    const float4* Y4 = reinterpret_cast<const float4*>(Y);
    float4 z[R_];
    #pragma unroll
    for (int r = 0; r < R_; r++) z[r] = make_float4(0.f, 0.f, 0.f, 0.f);

    for (int kc = 0; kc < KK; kc += 6) {          // 6 chunks x 6 loads (MLP=6)
        float4 y[6];
        #pragma unroll
        for (int j = 0; j < 6; j++)
            y[j] = Y4[(size_t)(kc + j) * HW4 + p4];
        #pragma unroll
        for (int j = 0; j < 6; j++) {
            #pragma unroll
            for (int r = 0; r < R_; r++) {
                float w = w2s[r*KK + kc + j];
                z[r].x = fmaf(w, y[j].x, z[r].x);
                z[r].y = fmaf(w, y[j].y, z[r].y);
                z[r].z = fmaf(w, y[j].z, z[r].z);
                z[r].w = fmaf(w, y[j].w, z[r].w);
            }
        }
    }

    const float4* x4 = reinterpret_cast<const float4*>(x);
    float4*       o4 = reinterpret_cast<float4*>(out);
    const size_t base = (size_t)l * C_ * HW4 + p4;

    for (int cc = 0; cc < C_; cc += 8) {
        float4 xv[8];
        #pragma unroll
        for (int j = 0; j < 8; j++)
            xv[j] = x4[base + (size_t)(cc + j) * HW4];
        #pragma unroll
        for (int j = 0; j < 8; j++) {
            float4 acc = make_float4(0.f, 0.f, 0.f, 0.f);
            const int c = cc + j;
            #pragma unroll
            for (int r = 0; r < R_; r++) {
                float w = w1s[c*R_ + r];
                acc.x = fmaf(w, z[r].x, acc.x);
                acc.y = fmaf(w, z[r].y, acc.y);
                acc.z = fmaf(w, z[r].z, acc.z);
                acc.w = fmaf(w, z[r].w, acc.w);
            }
            xv[j].x += acc.x;
            xv[j].y += acc.y;
            xv[j].z += acc.z;
            xv[j].w += acc.w;
            o4[base + (size_t)c * HW4] = xv[j];
        }
    }
}

// -------------------------------------------------------------------------
// launch.  Inputs (metadata order): x, Wa, ba, Wb, bb, gain, Y  (all f32)
// -------------------------------------------------------------------------
extern "C" void kernel_launch(void* const* d_in, const int* in_sizes, int n_in,
                              void* d_out, int out_size) {
    const float* x    = (const float*)d_in[0];
    const float* Wa   = (const float*)d_in[1];
    const float* ba   = (const float*)d_in[2];
    const float* Wb   = (const float*)d_in[3];
    const float* bb   = (const float*)d_in[4];
    const float* gain = (const float*)d_in[5];
    const float* Y    = (const float*)d_in[6];
    float* out = (float*)d_out;

    mean_kernel<<<L_*C_, 256>>>(x);
    hyper_kernel<<<(L_*WF + 255)/256, 256>>>(Wa, ba, Wb, bb, gain);
    apply_kernel<<<dim3((HW4 + 255)/256, L_), 256>>>(x, Y, out);
}